// round 3
// baseline (speedup 1.0000x reference)
#include <cuda_runtime.h>
#include <cuda_bf16.h>
#include <cstdint>

#define HDIM 128
#define MAXNODES 1000000

// ---- scratch (no allocation allowed) ----
__device__ float g_Wihf[3 * HDIM * HDIM];   // tf32-rounded weights
__device__ float g_Whhf[3 * HDIM * HDIM];
__device__ int g_winner[MAXNODES];

// ---- helpers ----
static __device__ __forceinline__ uint32_t smem_u32(const void* p) {
    uint32_t a;
    asm("{ .reg .u64 t; cvta.to.shared.u64 t, %1; cvt.u32.u64 %0, t; }" : "=r"(a) : "l"(p));
    return a;
}
// swizzles: xor low-3 bits of the 16B-group index with (row & 7)
static __device__ __forceinline__ uint32_t sw512(uint32_t r, uint32_t cb) {
    return (r << 9) + (cb ^ ((r & 7u) << 4));
}
static __device__ __forceinline__ uint32_t sw256(uint32_t r, uint32_t cb) {
    return (r << 8) + (cb ^ ((r & 7u) << 4));
}
static __device__ __forceinline__ uint32_t to_tf32(float x) {
    uint32_t u;
    asm("cvt.rna.tf32.f32 %0, %1;" : "=r"(u) : "f"(x));
    return u;
}
static __device__ __forceinline__ void sts128(uint32_t addr, uint32_t a, uint32_t b,
                                              uint32_t c, uint32_t d) {
    asm volatile("st.shared.v4.b32 [%0], {%1,%2,%3,%4};"
                 :: "r"(addr), "r"(a), "r"(b), "r"(c), "r"(d) : "memory");
}
static __device__ __forceinline__ void ldm_x4(uint32_t* r, uint32_t addr) {
    asm volatile("ldmatrix.sync.aligned.m8n8.x4.shared.b16 {%0,%1,%2,%3}, [%4];"
                 : "=r"(r[0]), "=r"(r[1]), "=r"(r[2]), "=r"(r[3]) : "r"(addr));
}
static __device__ __forceinline__ void mma_tf32(float* d, const uint32_t* a,
                                                uint32_t b0, uint32_t b1) {
    asm volatile(
        "mma.sync.aligned.m16n8k8.row.col.f32.tf32.tf32.f32 "
        "{%0,%1,%2,%3}, {%4,%5,%6,%7}, {%8,%9}, {%0,%1,%2,%3};"
        : "+f"(d[0]), "+f"(d[1]), "+f"(d[2]), "+f"(d[3])
        : "r"(a[0]), "r"(a[1]), "r"(a[2]), "r"(a[3]), "r"(b0), "r"(b1));
}
static __device__ __forceinline__ void cp16(uint32_t saddr, const void* gptr) {
    asm volatile("cp.async.cg.shared.global [%0], [%1], 16;"
                 :: "r"(saddr), "l"(gptr) : "memory");
}
static __device__ __forceinline__ void cp_commit() {
    asm volatile("cp.async.commit_group;" ::: "memory");
}
template <int N> static __device__ __forceinline__ void cp_wait() {
    asm volatile("cp.async.wait_group %0;" :: "n"(N) : "memory");
}
static __device__ __forceinline__ float fsigmoid(float x) {
    float e = __expf(-x);
    float r;
    asm("rcp.approx.f32 %0, %1;" : "=f"(r) : "f"(1.0f + e));
    return r;
}
static __device__ __forceinline__ float ftanh(float x) {
    float y;
    asm("tanh.approx.f32 %0, %1;" : "=f"(y) : "f"(x));
    return y;
}

// ---- kernel 1: tf32-round weights + winner reset ----
__global__ void prep_kernel(const float* __restrict__ Wih, const float* __restrict__ Whh,
                            int n_nodes) {
    int i = blockIdx.x * blockDim.x + threadIdx.x;
    int stride = gridDim.x * blockDim.x;
    for (int k = i; k < 3 * HDIM * HDIM; k += stride) {
        g_Wihf[k] = __uint_as_float(to_tf32(Wih[k]));
        g_Whhf[k] = __uint_as_float(to_tf32(Whh[k]));
    }
    for (int k = i; k < n_nodes; k += stride) g_winner[k] = -1;
}

// ---- kernel 2: last-writer-wins resolution ----
__global__ void winner_kernel(const int* __restrict__ ids, int batch) {
    int i = blockIdx.x * blockDim.x + threadIdx.x;
    if (i < batch) atomicMax(&g_winner[ids[i]], i);
}

// ---- one K=64 chunk of a 128x128 GEMM pass: acc += A[:,kc] @ Wchunk^T ----
// A tile: fp32(tf32) 128x128, pitch 512B, sw512. W chunk: 128n x 64k, pitch 256B, sw256.
static __device__ __forceinline__ void mma_chunk(uint32_t abase, uint32_t wbase,
                                                 float (&acc)[64], int lane, int wm, int wn,
                                                 int kc) {
    const uint32_t lr = (uint32_t)(lane & 7);
    const uint32_t lm = (uint32_t)(lane >> 3);          // 0..3 (tile selector)
    // A ldmatrix lane addr components
    const uint32_t a_row = (uint32_t)(wm * 32) + lr + ((lm & 1u) << 3);
    const uint32_t a_cb0 = (uint32_t)(kc * 256) + ((lm >> 1) << 4);
    // B ldmatrix lane addr components
    const uint32_t b_row = (uint32_t)(wn * 64) + lr + ((lm >> 1) << 3);
    const uint32_t b_cb0 = (lm & 1u) << 4;
#pragma unroll
    for (int ks = 0; ks < 8; ks++) {
        uint32_t a[2][4];
        ldm_x4(a[0], abase + sw512(a_row, a_cb0 + (uint32_t)(ks * 32)));
        ldm_x4(a[1], abase + sw512(a_row + 16, a_cb0 + (uint32_t)(ks * 32)));
#pragma unroll
        for (int np = 0; np < 4; np++) {
            uint32_t b[4];
            ldm_x4(b, wbase + sw256(b_row + (uint32_t)(np * 16),
                                    b_cb0 + (uint32_t)(ks * 32)));
#pragma unroll
            for (int mt = 0; mt < 2; mt++) {
                mma_tf32(&acc[(mt * 8 + np * 2) * 4], a[mt], b[0], b[1]);
                mma_tf32(&acc[(mt * 8 + np * 2 + 1) * 4], a[mt], b[2], b[3]);
            }
        }
    }
}

// ---- kernel 3: fused gather + GRU GEMM + scatter + winner-gated copy ----
// dyn smem: X(64K) + H(64K) + Wbuf0(32K) + Wbuf1(32K) = 192KB
#define SMEM_DYN (64 * 1024 + 64 * 1024 + 32 * 1024 + 32 * 1024)

__global__ void __launch_bounds__(256, 1)
gru_kernel(const int* __restrict__ ids, const float* __restrict__ X,
           const float* __restrict__ Mem, const float* __restrict__ b_ih,
           const float* __restrict__ b_hh, float* __restrict__ out,
           int batch, int n_nodes, int nodes_per_cta) {
    extern __shared__ char dsmem[];
    __shared__ int s_nid[128];
    __shared__ float s_bsr[128], s_bsz[128], s_bin[128], s_bhn[128];

    const int tid = threadIdx.x;
    const int lane = tid & 31;
    const int wid = tid >> 5;
    const int wm = wid & 3;       // 4 m-strips of 32 rows
    const int wn = wid >> 2;      // 2 n-strips of 64 cols

    const uint32_t sbase = smem_u32(dsmem);
    const uint32_t XS = sbase;
    const uint32_t HS = sbase + 64 * 1024;
    const uint32_t WB0 = sbase + 128 * 1024;
    const uint32_t WB1 = sbase + 160 * 1024;

    const int row0 = blockIdx.x * 128;
    int nrows = batch - row0;
    if (nrows > 128) nrows = 128;

    // copy range (winner<0 nodes handled by this CTA)
    const int cn0 = blockIdx.x * nodes_per_cta;
    int cn1 = cn0 + nodes_per_cta;
    if (cn1 > n_nodes) cn1 = n_nodes;
    const int copy_slots = (cn1 > cn0) ? (cn1 - cn0) * 32 : 0;  // float4 slots
    const int piece = (copy_slots + 11) / 12;

    // weight chunk sources in pass order (float element offsets):
    // P0: Wir, P1: Whr, P2: Whn, P3: Win, P4: Wiz, P5: Whz
    const float* wsrc[6];
    wsrc[0] = g_Wihf;          wsrc[1] = g_Whhf;
    wsrc[2] = g_Whhf + 32768;  wsrc[3] = g_Wihf + 32768;
    wsrc[4] = g_Wihf + 16384;  wsrc[5] = g_Whhf + 16384;

    // prefetch weight chunks 0 and 1 (chunk c: pass c>>1, kc = c&1, buffer c&1)
#pragma unroll
    for (int c = 0; c < 2; c++) {
        const uint32_t wb = (c & 1) ? WB1 : WB0;
        const float* src = wsrc[c >> 1] + (c & 1) * 64;
#pragma unroll
        for (int j = 0; j < 8; j++) {
            int ci = tid + j * 256;
            uint32_t n = (uint32_t)(ci >> 4), gi = (uint32_t)(ci & 15);
            cp16(wb + sw256(n, gi << 4), src + (size_t)n * 128 + gi * 4);
        }
        cp_commit();
    }

    if (tid < 128) {
        s_nid[tid] = (tid < nrows) ? ids[row0 + tid] : 0;
        s_bsr[tid] = b_ih[tid] + b_hh[tid];
        s_bsz[tid] = b_ih[128 + tid] + b_hh[128 + tid];
        s_bin[tid] = b_ih[256 + tid];
        s_bhn[tid] = b_hh[256 + tid];
    }
    __syncthreads();   // s_nid visible for H gather

    // fill X tile (tf32-rounded fp32, sw512)
#pragma unroll
    for (int j = 0; j < 16; j++) {
        int idx = tid + j * 256;           // float4 slot: row = idx>>5, group = idx&31
        int r = idx >> 5, fq = idx & 31;
        float4 v = make_float4(0.f, 0.f, 0.f, 0.f);
        if (r < nrows) v = *(const float4*)(X + (size_t)(row0 + r) * HDIM + fq * 4);
        sts128(XS + sw512((uint32_t)r, (uint32_t)(fq << 4)),
               to_tf32(v.x), to_tf32(v.y), to_tf32(v.z), to_tf32(v.w));
    }
    // fill H tile (gathered, tf32-rounded)
#pragma unroll
    for (int j = 0; j < 16; j++) {
        int idx = tid + j * 256;
        int r = idx >> 5, fq = idx & 31;
        float4 v = make_float4(0.f, 0.f, 0.f, 0.f);
        if (r < nrows) v = *(const float4*)(Mem + (size_t)s_nid[r] * HDIM + fq * 4);
        sts128(HS + sw512((uint32_t)r, (uint32_t)(fq << 4)),
               to_tf32(v.x), to_tf32(v.y), to_tf32(v.z), to_tf32(v.w));
    }

    float accA[64], keep[64];
#pragma unroll
    for (int e = 0; e < 64; e++) accA[e] = 0.f;

    const int colbase = wn * 64 + 2 * (lane & 3);
    // A-tile per pass: P0:X P1:H P2:H P3:X P4:X P5:H
    const uint32_t atile[6] = {XS, HS, HS, XS, XS, HS};

#pragma unroll
    for (int c = 0; c < 12; c++) {
        if (c < 11) cp_wait<1>(); else cp_wait<0>();
        __syncthreads();
        const uint32_t wb = (c & 1) ? WB1 : WB0;
        mma_chunk(atile[c >> 1], wb, accA, lane, wm, wn, c & 1);
        __syncthreads();
        if (c + 2 < 12) {   // prefetch chunk c+2 into freed buffer
            const float* src = wsrc[(c + 2) >> 1] + ((c + 2) & 1) * 64;
#pragma unroll
            for (int j = 0; j < 8; j++) {
                int ci = tid + j * 256;
                uint32_t n = (uint32_t)(ci >> 4), gi = (uint32_t)(ci & 15);
                cp16(wb + sw256(n, gi << 4), src + (size_t)n * 128 + gi * 4);
            }
            cp_commit();
        }
        // interleaved winner-gated copy piece (overlaps HBM with tensor work)
        {
            int lo = c * piece + tid;
            int hi = (c + 1) * piece;
            if (hi > copy_slots) hi = copy_slots;
            for (int i = lo; i < hi; i += 256) {
                int node = cn0 + (i >> 5);
                if (g_winner[node] < 0) {
                    const float4* s = (const float4*)(Mem + (size_t)node * HDIM) + (i & 31);
                    float4* d = (float4*)(out + (size_t)node * HDIM) + (i & 31);
                    *d = *s;
                }
            }
        }
        // gate activations at pass boundaries
        if (c == 3) {           // r = sigmoid(X·Wir + H·Whr + b)
#pragma unroll
            for (int e = 0; e < 64; e++) {
                int col = colbase + (((e >> 2) & 7) << 3) + (e & 1);
                keep[e] = fsigmoid(accA[e] + s_bsr[col]);
                accA[e] = 0.f;
            }
        } else if (c == 5) {    // p = r * (H·Whn + bhn)
#pragma unroll
            for (int e = 0; e < 64; e++) {
                int col = colbase + (((e >> 2) & 7) << 3) + (e & 1);
                keep[e] = keep[e] * (accA[e] + s_bhn[col]);
                accA[e] = 0.f;
            }
        } else if (c == 7) {    // n = tanh(X·Win + bin + p)
#pragma unroll
            for (int e = 0; e < 64; e++) {
                int col = colbase + (((e >> 2) & 7) << 3) + (e & 1);
                keep[e] = ftanh(accA[e] + s_bin[col] + keep[e]);
                accA[e] = 0.f;
            }
        }
    }

    // epilogue: z = sigmoid(acc + bz); out = (1-z)*n + z*h  (h fp32 from global)
#pragma unroll
    for (int mt = 0; mt < 2; mt++) {
#pragma unroll
        for (int rr = 0; rr < 2; rr++) {
            const int row = wm * 32 + mt * 16 + (lane >> 2) + rr * 8;
            const int node = s_nid[row];
            const bool wr = (row < nrows) && (g_winner[node] == row0 + row);
#pragma unroll
            for (int nt = 0; nt < 8; nt++) {
                const int col = colbase + nt * 8;
                const int e = (mt * 8 + nt) * 4 + rr * 2;
                float z0 = fsigmoid(accA[e] + s_bsz[col]);
                float z1 = fsigmoid(accA[e + 1] + s_bsz[col + 1]);
                float2 h = *(const float2*)(Mem + (size_t)node * HDIM + col);
                float o0 = (1.f - z0) * keep[e] + z0 * h.x;
                float o1 = (1.f - z1) * keep[e + 1] + z1 * h.y;
                if (wr) *(float2*)(out + (size_t)node * HDIM + col) = make_float2(o0, o1);
            }
        }
    }
}

// ---- launch ----
extern "C" void kernel_launch(void* const* d_in, const int* in_sizes, int n_in,
                              void* d_out, int out_size) {
    const int* ids = (const int*)d_in[0];
    const float* msgs = (const float*)d_in[1];
    const float* mem = (const float*)d_in[2];
    const float* Wih = (const float*)d_in[3];
    const float* Whh = (const float*)d_in[4];
    const float* bih = (const float*)d_in[5];
    const float* bhh = (const float*)d_in[6];
    float* out = (float*)d_out;

    const int batch = in_sizes[0];
    const int n_nodes = in_sizes[2] / HDIM;
    const int gcta = (batch + 127) / 128;
    const int nodes_per_cta = (n_nodes + gcta - 1) / gcta;

    cudaFuncSetAttribute(gru_kernel, cudaFuncAttributeMaxDynamicSharedMemorySize, SMEM_DYN);

    prep_kernel<<<256, 256>>>(Wih, Whh, n_nodes);
    winner_kernel<<<(batch + 255) / 256, 256>>>(ids, batch);
    gru_kernel<<<gcta, 256, SMEM_DYN>>>(ids, msgs, mem, bih, bhh, out,
                                        batch, n_nodes, nodes_per_cta);
}

// round 4
// speedup vs baseline: 1.7006x; 1.7006x over previous
#include <cuda_runtime.h>
#include <cuda_bf16.h>
#include <cstdint>

#define HDIM 128
#define MAXNODES 1000000

// ---- scratch (no allocation allowed) ----
__device__ float g_Wihf[3 * HDIM * HDIM];   // tf32-rounded weights
__device__ float g_Whhf[3 * HDIM * HDIM];
__device__ int g_winner[MAXNODES];

// ---- helpers ----
static __device__ __forceinline__ uint32_t smem_u32(const void* p) {
    uint32_t a;
    asm("{ .reg .u64 t; cvta.to.shared.u64 t, %1; cvt.u32.u64 %0, t; }" : "=r"(a) : "l"(p));
    return a;
}
// swizzles: xor low-3 bits of the 16B-group index with (row & 7)
static __device__ __forceinline__ uint32_t sw512(uint32_t r, uint32_t cb) {
    return (r << 9) + (cb ^ ((r & 7u) << 4));
}
static __device__ __forceinline__ uint32_t sw256(uint32_t r, uint32_t cb) {
    return (r << 8) + (cb ^ ((r & 7u) << 4));
}
static __device__ __forceinline__ uint32_t to_tf32(float x) {
    uint32_t u;
    asm("cvt.rna.tf32.f32 %0, %1;" : "=r"(u) : "f"(x));
    return u;
}
static __device__ __forceinline__ void sts128(uint32_t addr, uint32_t a, uint32_t b,
                                              uint32_t c, uint32_t d) {
    asm volatile("st.shared.v4.b32 [%0], {%1,%2,%3,%4};"
                 :: "r"(addr), "r"(a), "r"(b), "r"(c), "r"(d) : "memory");
}
static __device__ __forceinline__ void ldm_x4(uint32_t* r, uint32_t addr) {
    asm volatile("ldmatrix.sync.aligned.m8n8.x4.shared.b16 {%0,%1,%2,%3}, [%4];"
                 : "=r"(r[0]), "=r"(r[1]), "=r"(r[2]), "=r"(r[3]) : "r"(addr));
}
static __device__ __forceinline__ void mma_tf32(float* d, const uint32_t* a,
                                                uint32_t b0, uint32_t b1) {
    asm volatile(
        "mma.sync.aligned.m16n8k8.row.col.f32.tf32.tf32.f32 "
        "{%0,%1,%2,%3}, {%4,%5,%6,%7}, {%8,%9}, {%0,%1,%2,%3};"
        : "+f"(d[0]), "+f"(d[1]), "+f"(d[2]), "+f"(d[3])
        : "r"(a[0]), "r"(a[1]), "r"(a[2]), "r"(a[3]), "r"(b0), "r"(b1));
}
static __device__ __forceinline__ void cp16(uint32_t saddr, const void* gptr) {
    asm volatile("cp.async.cg.shared.global [%0], [%1], 16;"
                 :: "r"(saddr), "l"(gptr) : "memory");
}
static __device__ __forceinline__ void cp_commit() {
    asm volatile("cp.async.commit_group;" ::: "memory");
}
template <int N> static __device__ __forceinline__ void cp_wait() {
    asm volatile("cp.async.wait_group %0;" :: "n"(N) : "memory");
}
static __device__ __forceinline__ float fsigmoid(float x) {
    float e = __expf(-x);
    float r;
    asm("rcp.approx.f32 %0, %1;" : "=f"(r) : "f"(1.0f + e));
    return r;
}
static __device__ __forceinline__ float ftanh(float x) {
    float y;
    asm("tanh.approx.f32 %0, %1;" : "=f"(y) : "f"(x));
    return y;
}

// ---- kernel 1: tf32-round weights + winner reset ----
__global__ void prep_kernel(const float* __restrict__ Wih, const float* __restrict__ Whh,
                            int n_nodes) {
    int i = blockIdx.x * blockDim.x + threadIdx.x;
    int stride = gridDim.x * blockDim.x;
    for (int k = i; k < 3 * HDIM * HDIM; k += stride) {
        g_Wihf[k] = __uint_as_float(to_tf32(Wih[k]));
        g_Whhf[k] = __uint_as_float(to_tf32(Whh[k]));
    }
    for (int k = i; k < n_nodes; k += stride) g_winner[k] = -1;
}

// ---- kernel 2: last-writer-wins resolution ----
__global__ void winner_kernel(const int* __restrict__ ids, int batch) {
    int i = blockIdx.x * blockDim.x + threadIdx.x;
    if (i < batch) atomicMax(&g_winner[ids[i]], i);
}

// ---- one K=64 chunk of a 128x128 GEMM pass: acc += A[:,kc] @ Wchunk^T ----
static __device__ __forceinline__ void mma_chunk(uint32_t abase, uint32_t wbase,
                                                 float (&acc)[64], int lane, int wm, int wn,
                                                 int kc) {
    const uint32_t lr = (uint32_t)(lane & 7);
    const uint32_t lm = (uint32_t)(lane >> 3);
    const uint32_t a_row = (uint32_t)(wm * 32) + lr + ((lm & 1u) << 3);
    const uint32_t a_cb0 = (uint32_t)(kc * 256) + ((lm >> 1) << 4);
    const uint32_t b_row = (uint32_t)(wn * 64) + lr + ((lm >> 1) << 3);
    const uint32_t b_cb0 = (lm & 1u) << 4;
#pragma unroll
    for (int ks = 0; ks < 8; ks++) {
        uint32_t a[2][4];
        ldm_x4(a[0], abase + sw512(a_row, a_cb0 + (uint32_t)(ks * 32)));
        ldm_x4(a[1], abase + sw512(a_row + 16, a_cb0 + (uint32_t)(ks * 32)));
#pragma unroll
        for (int np = 0; np < 4; np++) {
            uint32_t b[4];
            ldm_x4(b, wbase + sw256(b_row + (uint32_t)(np * 16),
                                    b_cb0 + (uint32_t)(ks * 32)));
#pragma unroll
            for (int mt = 0; mt < 2; mt++) {
                mma_tf32(&acc[(mt * 8 + np * 2) * 4], a[mt], b[0], b[1]);
                mma_tf32(&acc[(mt * 8 + np * 2 + 1) * 4], a[mt], b[2], b[3]);
            }
        }
    }
}

// ---- fused kernel: role by blockIdx (3 GRU : 2 copy interleave) ----
// dyn smem (GRU role): X(64K) + H(64K) + Wbuf0(32K) + Wbuf1(32K) = 192KB
#define SMEM_DYN (64 * 1024 + 64 * 1024 + 32 * 1024 + 32 * 1024)

__global__ void __launch_bounds__(256, 1)
gru_kernel(const int* __restrict__ ids, const float* __restrict__ X,
           const float* __restrict__ Mem, const float* __restrict__ b_ih,
           const float* __restrict__ b_hh, float* __restrict__ out,
           int batch, int n_nodes, int gcta, int ccta, int npc) {
    const int p = blockIdx.x / 5;
    const int rrole = blockIdx.x % 5;

    const int tid = threadIdx.x;
    const int lane = tid & 31;
    const int wid = tid >> 5;

    if (rrole >= 3) {
        // ================= COPY ROLE =================
        const int ci = p * 2 + (rrole - 3);
        if (ci >= ccta) return;
        const int node0 = ci * npc;
        int node1 = node0 + npc;
        if (node1 > n_nodes) node1 = n_nodes;
        // warp per node, 4-node lookahead for MLP
        for (int n = node0 + wid * 4; n < node1; n += 32) {
            const int lim = node1 - n;
            int w[4];
            float4 v[4];
#pragma unroll
            for (int j = 0; j < 4; j++)
                w[j] = (j < lim) ? g_winner[n + j] : 0;
#pragma unroll
            for (int j = 0; j < 4; j++)
                if (j < lim && w[j] < 0)
                    v[j] = ((const float4*)(Mem + (size_t)(n + j) * HDIM))[lane];
#pragma unroll
            for (int j = 0; j < 4; j++)
                if (j < lim && w[j] < 0)
                    ((float4*)(out + (size_t)(n + j) * HDIM))[lane] = v[j];
        }
        return;
    }

    // ================= GRU ROLE =================
    const int g = p * 3 + rrole;
    if (g >= gcta) return;

    extern __shared__ char dsmem[];
    __shared__ int s_nid[128];
    __shared__ float s_bsr[128], s_bsz[128], s_bin[128], s_bhn[128];

    const int wm = wid & 3;
    const int wn = wid >> 2;

    const uint32_t sbase = smem_u32(dsmem);
    const uint32_t XS = sbase;
    const uint32_t HS = sbase + 64 * 1024;
    const uint32_t WB0 = sbase + 128 * 1024;
    const uint32_t WB1 = sbase + 160 * 1024;

    const int row0 = g * 128;
    int nrows = batch - row0;
    if (nrows > 128) nrows = 128;

    // weight chunk sources in pass order (float offsets):
    // P0: Wir, P1: Whr, P2: Whn, P3: Win, P4: Wiz, P5: Whz
    const float* wsrc[6];
    wsrc[0] = g_Wihf;          wsrc[1] = g_Whhf;
    wsrc[2] = g_Whhf + 32768;  wsrc[3] = g_Wihf + 32768;
    wsrc[4] = g_Wihf + 16384;  wsrc[5] = g_Whhf + 16384;

    // prefetch weight chunks 0 and 1
#pragma unroll
    for (int c = 0; c < 2; c++) {
        const uint32_t wb = (c & 1) ? WB1 : WB0;
        const float* src = wsrc[c >> 1] + (c & 1) * 64;
#pragma unroll
        for (int j = 0; j < 8; j++) {
            int ci = tid + j * 256;
            uint32_t n = (uint32_t)(ci >> 4), gi = (uint32_t)(ci & 15);
            cp16(wb + sw256(n, gi << 4), src + (size_t)n * 128 + gi * 4);
        }
        cp_commit();
    }

    if (tid < 128) {
        s_nid[tid] = (tid < nrows) ? ids[row0 + tid] : 0;
        s_bsr[tid] = b_ih[tid] + b_hh[tid];
        s_bsz[tid] = b_ih[128 + tid] + b_hh[128 + tid];
        s_bin[tid] = b_ih[256 + tid];
        s_bhn[tid] = b_hh[256 + tid];
    }
    __syncthreads();

    // fill X tile (tf32-rounded fp32, sw512)
#pragma unroll
    for (int j = 0; j < 16; j++) {
        int idx = tid + j * 256;
        int r = idx >> 5, fq = idx & 31;
        float4 v = make_float4(0.f, 0.f, 0.f, 0.f);
        if (r < nrows) v = *(const float4*)(X + (size_t)(row0 + r) * HDIM + fq * 4);
        sts128(XS + sw512((uint32_t)r, (uint32_t)(fq << 4)),
               to_tf32(v.x), to_tf32(v.y), to_tf32(v.z), to_tf32(v.w));
    }
    // fill H tile (gathered, tf32-rounded)
#pragma unroll
    for (int j = 0; j < 16; j++) {
        int idx = tid + j * 256;
        int r = idx >> 5, fq = idx & 31;
        float4 v = make_float4(0.f, 0.f, 0.f, 0.f);
        if (r < nrows) v = *(const float4*)(Mem + (size_t)s_nid[r] * HDIM + fq * 4);
        sts128(HS + sw512((uint32_t)r, (uint32_t)(fq << 4)),
               to_tf32(v.x), to_tf32(v.y), to_tf32(v.z), to_tf32(v.w));
    }

    float accA[64], keep[64];
#pragma unroll
    for (int e = 0; e < 64; e++) accA[e] = 0.f;

    const int colbase = wn * 64 + 2 * (lane & 3);
    const uint32_t atile[6] = {XS, HS, HS, XS, XS, HS};

#pragma unroll
    for (int c = 0; c < 12; c++) {
        if (c < 11) cp_wait<1>(); else cp_wait<0>();
        __syncthreads();
        const uint32_t wb = (c & 1) ? WB1 : WB0;
        mma_chunk(atile[c >> 1], wb, accA, lane, wm, wn, c & 1);
        __syncthreads();
        if (c + 2 < 12) {
            const float* src = wsrc[(c + 2) >> 1] + ((c + 2) & 1) * 64;
#pragma unroll
            for (int j = 0; j < 8; j++) {
                int ci = tid + j * 256;
                uint32_t n = (uint32_t)(ci >> 4), gi = (uint32_t)(ci & 15);
                cp16(wb + sw256(n, gi << 4), src + (size_t)n * 128 + gi * 4);
            }
            cp_commit();
        }
        if (c == 3) {           // r = sigmoid(X·Wir + H·Whr + b)
#pragma unroll
            for (int e = 0; e < 64; e++) {
                int col = colbase + (((e >> 2) & 7) << 3) + (e & 1);
                keep[e] = fsigmoid(accA[e] + s_bsr[col]);
                accA[e] = 0.f;
            }
        } else if (c == 5) {    // p = r * (H·Whn + bhn)
#pragma unroll
            for (int e = 0; e < 64; e++) {
                int col = colbase + (((e >> 2) & 7) << 3) + (e & 1);
                keep[e] = keep[e] * (accA[e] + s_bhn[col]);
                accA[e] = 0.f;
            }
        } else if (c == 7) {    // n = tanh(X·Win + bin + p)
#pragma unroll
            for (int e = 0; e < 64; e++) {
                int col = colbase + (((e >> 2) & 7) << 3) + (e & 1);
                keep[e] = ftanh(accA[e] + s_bin[col] + keep[e]);
                accA[e] = 0.f;
            }
        }
    }

    // epilogue: z = sigmoid(acc + bz); out = (1-z)*n + z*h
#pragma unroll
    for (int mt = 0; mt < 2; mt++) {
#pragma unroll
        for (int rr = 0; rr < 2; rr++) {
            const int row = wm * 32 + mt * 16 + (lane >> 2) + rr * 8;
            const int node = s_nid[row];
            const bool wr = (row < nrows) && (g_winner[node] == row0 + row);
#pragma unroll
            for (int nt = 0; nt < 8; nt++) {
                const int col = colbase + nt * 8;
                const int e = (mt * 8 + nt) * 4 + rr * 2;
                float z0 = fsigmoid(accA[e] + s_bsz[col]);
                float z1 = fsigmoid(accA[e + 1] + s_bsz[col + 1]);
                float2 h = *(const float2*)(Mem + (size_t)node * HDIM + col);
                float o0 = (1.f - z0) * keep[e] + z0 * h.x;
                float o1 = (1.f - z1) * keep[e + 1] + z1 * h.y;
                if (wr) *(float2*)(out + (size_t)node * HDIM + col) = make_float2(o0, o1);
            }
        }
    }
}

// ---- launch ----
extern "C" void kernel_launch(void* const* d_in, const int* in_sizes, int n_in,
                              void* d_out, int out_size) {
    const int* ids = (const int*)d_in[0];
    const float* msgs = (const float*)d_in[1];
    const float* mem = (const float*)d_in[2];
    const float* Wih = (const float*)d_in[3];
    const float* Whh = (const float*)d_in[4];
    const float* bih = (const float*)d_in[5];
    const float* bhh = (const float*)d_in[6];
    float* out = (float*)d_out;

    const int batch = in_sizes[0];
    const int n_nodes = in_sizes[2] / HDIM;
    const int gcta = (batch + 127) / 128;
    const int periods = (gcta + 2) / 3;
    const int ccta = periods * 2;
    const int npc = (n_nodes + ccta - 1) / ccta;
    const int grid = periods * 5;

    cudaFuncSetAttribute(gru_kernel, cudaFuncAttributeMaxDynamicSharedMemorySize, SMEM_DYN);

    prep_kernel<<<256, 256>>>(Wih, Whh, n_nodes);
    winner_kernel<<<(batch + 255) / 256, 256>>>(ids, batch);
    gru_kernel<<<grid, 256, SMEM_DYN>>>(ids, msgs, mem, bih, bhh, out,
                                        batch, n_nodes, gcta, ccta, npc);
}

// round 5
// speedup vs baseline: 2.3792x; 1.3991x over previous
#include <cuda_runtime.h>
#include <cuda_bf16.h>
#include <cstdint>

#define HDIM 128
#define MAXNODES 1000000

// ---- scratch (no allocation allowed) ----
__device__ float g_Wihf[3 * HDIM * HDIM];   // tf32(RNA)-rounded weights
__device__ float g_Whhf[3 * HDIM * HDIM];
__device__ int g_winner[MAXNODES];

// ---- helpers ----
static __device__ __forceinline__ uint32_t smem_u32(const void* p) {
    uint32_t a;
    asm("{ .reg .u64 t; cvta.to.shared.u64 t, %1; cvt.u32.u64 %0, t; }" : "=r"(a) : "l"(p));
    return a;
}
static __device__ __forceinline__ uint32_t sw512(uint32_t r, uint32_t cb) {
    return (r << 9) + (cb ^ ((r & 7u) << 4));
}
static __device__ __forceinline__ uint32_t sw256(uint32_t r, uint32_t cb) {
    return (r << 8) + (cb ^ ((r & 7u) << 4));
}
static __device__ __forceinline__ uint32_t to_tf32(float x) {
    uint32_t u;
    asm("cvt.rna.tf32.f32 %0, %1;" : "=r"(u) : "f"(x));
    return u;
}
static __device__ __forceinline__ void ldm_x4(uint32_t* r, uint32_t addr) {
    asm volatile("ldmatrix.sync.aligned.m8n8.x4.shared.b16 {%0,%1,%2,%3}, [%4];"
                 : "=r"(r[0]), "=r"(r[1]), "=r"(r[2]), "=r"(r[3]) : "r"(addr));
}
static __device__ __forceinline__ void mma_tf32(float* d, const uint32_t* a,
                                                uint32_t b0, uint32_t b1) {
    asm volatile(
        "mma.sync.aligned.m16n8k8.row.col.f32.tf32.tf32.f32 "
        "{%0,%1,%2,%3}, {%4,%5,%6,%7}, {%8,%9}, {%0,%1,%2,%3};"
        : "+f"(d[0]), "+f"(d[1]), "+f"(d[2]), "+f"(d[3])
        : "r"(a[0]), "r"(a[1]), "r"(a[2]), "r"(a[3]), "r"(b0), "r"(b1));
}
static __device__ __forceinline__ void cp16(uint32_t saddr, const void* gptr) {
    asm volatile("cp.async.cg.shared.global [%0], [%1], 16;"
                 :: "r"(saddr), "l"(gptr) : "memory");
}
// predicated cp.async: pred=false -> zero-fill 16B (src not read)
static __device__ __forceinline__ void cp16p(uint32_t saddr, const void* gptr, bool pred) {
    int sz = pred ? 16 : 0;
    asm volatile("cp.async.cg.shared.global [%0], [%1], 16, %2;"
                 :: "r"(saddr), "l"(gptr), "r"(sz) : "memory");
}
static __device__ __forceinline__ void cp_commit() {
    asm volatile("cp.async.commit_group;" ::: "memory");
}
template <int N> static __device__ __forceinline__ void cp_wait() {
    asm volatile("cp.async.wait_group %0;" :: "n"(N) : "memory");
}
static __device__ __forceinline__ float fsigmoid(float x) {
    float e = __expf(-x);
    float r;
    asm("rcp.approx.f32 %0, %1;" : "=f"(r) : "f"(1.0f + e));
    return r;
}
static __device__ __forceinline__ float ftanh(float x) {
    float y;
    asm("tanh.approx.f32 %0, %1;" : "=f"(y) : "f"(x));
    return y;
}

// ---- kernel 1: tf32-round weights (RNA) + winner reset ----
__global__ void prep_kernel(const float* __restrict__ Wih, const float* __restrict__ Whh,
                            int n_nodes) {
    int i = blockIdx.x * blockDim.x + threadIdx.x;
    int stride = gridDim.x * blockDim.x;
    for (int k = i; k < 3 * HDIM * HDIM; k += stride) {
        g_Wihf[k] = __uint_as_float(to_tf32(Wih[k]));
        g_Whhf[k] = __uint_as_float(to_tf32(Whh[k]));
    }
    for (int k = i; k < n_nodes; k += stride) g_winner[k] = -1;
}

// ---- kernel 2: last-writer-wins resolution ----
__global__ void winner_kernel(const int* __restrict__ ids, int batch) {
    int i = blockIdx.x * blockDim.x + threadIdx.x;
    if (i < batch) atomicMax(&g_winner[ids[i]], i);
}

// ---- one K=64 chunk of a 128x128 GEMM pass: acc += A[:,kc] @ Wchunk^T ----
static __device__ __forceinline__ void mma_chunk(uint32_t abase, uint32_t wbase,
                                                 float (&acc)[64], int lane, int wm, int wn,
                                                 int kc) {
    const uint32_t lr = (uint32_t)(lane & 7);
    const uint32_t lm = (uint32_t)(lane >> 3);
    const uint32_t a_row = (uint32_t)(wm * 32) + lr + ((lm & 1u) << 3);
    const uint32_t a_cb0 = (uint32_t)(kc * 256) + ((lm >> 1) << 4);
    const uint32_t b_row = (uint32_t)(wn * 64) + lr + ((lm >> 1) << 3);
    const uint32_t b_cb0 = (lm & 1u) << 4;
#pragma unroll
    for (int ks = 0; ks < 8; ks++) {
        uint32_t a[2][4];
        ldm_x4(a[0], abase + sw512(a_row, a_cb0 + (uint32_t)(ks * 32)));
        ldm_x4(a[1], abase + sw512(a_row + 16, a_cb0 + (uint32_t)(ks * 32)));
#pragma unroll
        for (int np = 0; np < 4; np++) {
            uint32_t b[4];
            ldm_x4(b, wbase + sw256(b_row + (uint32_t)(np * 16),
                                    b_cb0 + (uint32_t)(ks * 32)));
#pragma unroll
            for (int mt = 0; mt < 2; mt++) {
                mma_tf32(&acc[(mt * 8 + np * 2) * 4], a[mt], b[0], b[1]);
                mma_tf32(&acc[(mt * 8 + np * 2 + 1) * 4], a[mt], b[2], b[3]);
            }
        }
    }
}

// ---- fused kernel: role by blockIdx (3 GRU : 2 copy interleave) ----
// dyn smem (GRU role): X(64K) + H(64K) + Wbuf0(32K) + Wbuf1(32K) = 192KB
#define SMEM_DYN (64 * 1024 + 64 * 1024 + 32 * 1024 + 32 * 1024)

__global__ void __launch_bounds__(256, 1)
gru_kernel(const int* __restrict__ ids, const float* __restrict__ X,
           const float* __restrict__ Mem, const float* __restrict__ b_ih,
           const float* __restrict__ b_hh, float* __restrict__ out,
           int batch, int n_nodes, int gcta, int ccta, int npc) {
    const int p = blockIdx.x / 5;
    const int rrole = blockIdx.x % 5;

    const int tid = threadIdx.x;
    const int lane = tid & 31;
    const int wid = tid >> 5;

    if (rrole >= 3) {
        // ================= COPY ROLE =================
        const int ci = p * 2 + (rrole - 3);
        if (ci >= ccta) return;
        const int node0 = ci * npc;
        int node1 = node0 + npc;
        if (node1 > n_nodes) node1 = n_nodes;
        // warp per 8 nodes; winner + value loads issued unconditionally in parallel
        for (int base = node0 + wid * 8; base < node1; base += 64) {
            const int lim = node1 - base;
            int w[8];
            float4 v[8];
#pragma unroll
            for (int j = 0; j < 8; j++)
                w[j] = (j < lim) ? g_winner[base + j] : 0;
#pragma unroll
            for (int j = 0; j < 8; j++)
                if (j < lim)
                    v[j] = ((const float4*)(Mem + (size_t)(base + j) * HDIM))[lane];
#pragma unroll
            for (int j = 0; j < 8; j++)
                if (j < lim && w[j] < 0)
                    ((float4*)(out + (size_t)(base + j) * HDIM))[lane] = v[j];
        }
        return;
    }

    // ================= GRU ROLE =================
    const int g = p * 3 + rrole;
    if (g >= gcta) return;

    extern __shared__ char dsmem[];
    __shared__ int s_nid[128];
    __shared__ float s_bsr[128], s_bsz[128], s_bin[128], s_bhn[128];

    const int wm = wid & 3;
    const int wn = wid >> 2;

    const uint32_t sbase = smem_u32(dsmem);
    const uint32_t XS = sbase;
    const uint32_t HS = sbase + 64 * 1024;
    const uint32_t WB0 = sbase + 128 * 1024;
    const uint32_t WB1 = sbase + 160 * 1024;

    const int row0 = g * 128;
    int nrows = batch - row0;
    if (nrows > 128) nrows = 128;

    // X tile: raw fp32 via cp.async (HW truncates to tf32 in MMA)
#pragma unroll
    for (int j = 0; j < 16; j++) {
        int idx = tid + j * 256;
        int r = idx >> 5, fq = idx & 31;
        cp16p(XS + sw512((uint32_t)r, (uint32_t)(fq << 4)),
              X + (size_t)(row0 + r) * HDIM + fq * 4, r < nrows);
    }
    // H tile: gathered rows, raw fp32 via cp.async (exact -> reused in epilogue)
    {
        int nidv[16];
#pragma unroll
        for (int j = 0; j < 16; j++) {
            int r = (tid + j * 256) >> 5;
            nidv[j] = (r < nrows) ? __ldg(ids + row0 + r) : 0;
        }
#pragma unroll
        for (int j = 0; j < 16; j++) {
            int idx = tid + j * 256;
            int r = idx >> 5, fq = idx & 31;
            cp16p(HS + sw512((uint32_t)r, (uint32_t)(fq << 4)),
                  Mem + (size_t)nidv[j] * HDIM + fq * 4, r < nrows);
        }
    }
    cp_commit();   // group: XH

    // weight chunk sources in pass order (float offsets):
    // P0: Wir, P1: Whr, P2: Whn, P3: Win, P4: Wiz, P5: Whz
    const float* wsrc[6];
    wsrc[0] = g_Wihf;          wsrc[1] = g_Whhf;
    wsrc[2] = g_Whhf + 32768;  wsrc[3] = g_Wihf + 32768;
    wsrc[4] = g_Wihf + 16384;  wsrc[5] = g_Whhf + 16384;

    // prefetch weight chunks 0 and 1 (chunk c: pass c>>1, kc = c&1)
#pragma unroll
    for (int c = 0; c < 2; c++) {
        const uint32_t wb = (c & 1) ? WB1 : WB0;
        const float* src = wsrc[c >> 1] + (c & 1) * 64;
#pragma unroll
        for (int j = 0; j < 8; j++) {
            int ci = tid + j * 256;
            uint32_t n = (uint32_t)(ci >> 4), gi = (uint32_t)(ci & 15);
            cp16(wb + sw256(n, gi << 4), src + (size_t)n * 128 + gi * 4);
        }
        cp_commit();
    }

    if (tid < 128) {
        s_nid[tid] = (tid < nrows) ? ids[row0 + tid] : 0;
        s_bsr[tid] = b_ih[tid] + b_hh[tid];
        s_bsz[tid] = b_ih[128 + tid] + b_hh[128 + tid];
        s_bin[tid] = b_ih[256 + tid];
        s_bhn[tid] = b_hh[256 + tid];
    }

    float accA[64], keep[64];
#pragma unroll
    for (int e = 0; e < 64; e++) accA[e] = 0.f;

    const int colbase = wn * 64 + 2 * (lane & 3);
    const uint32_t atile[6] = {XS, HS, HS, XS, XS, HS};

#pragma unroll
    for (int c = 0; c < 12; c++) {
        if (c < 11) cp_wait<1>(); else cp_wait<0>();
        __syncthreads();
        const uint32_t wb = (c & 1) ? WB1 : WB0;
        mma_chunk(atile[c >> 1], wb, accA, lane, wm, wn, c & 1);
        __syncthreads();
        if (c + 2 < 12) {
            const float* src = wsrc[(c + 2) >> 1] + ((c + 2) & 1) * 64;
#pragma unroll
            for (int j = 0; j < 8; j++) {
                int ci = tid + j * 256;
                uint32_t n = (uint32_t)(ci >> 4), gi = (uint32_t)(ci & 15);
                cp16(wb + sw256(n, gi << 4), src + (size_t)n * 128 + gi * 4);
            }
            cp_commit();
        }
        if (c == 3) {           // r = sigmoid(X·Wir + H·Whr + b)
#pragma unroll
            for (int e = 0; e < 64; e++) {
                int col = colbase + (((e >> 2) & 7) << 3) + (e & 1);
                keep[e] = fsigmoid(accA[e] + s_bsr[col]);
                accA[e] = 0.f;
            }
        } else if (c == 5) {    // p = r * (H·Whn + bhn)
#pragma unroll
            for (int e = 0; e < 64; e++) {
                int col = colbase + (((e >> 2) & 7) << 3) + (e & 1);
                keep[e] = keep[e] * (accA[e] + s_bhn[col]);
                accA[e] = 0.f;
            }
        } else if (c == 7) {    // n = tanh(X·Win + bin + p)
#pragma unroll
            for (int e = 0; e < 64; e++) {
                int col = colbase + (((e >> 2) & 7) << 3) + (e & 1);
                keep[e] = ftanh(accA[e] + s_bin[col] + keep[e]);
                accA[e] = 0.f;
            }
        }
    }

    // epilogue: z = sigmoid(acc + bz); out = (1-z)*n + z*h  (h exact from SMEM H tile)
    const char* hbase = dsmem + 64 * 1024;
#pragma unroll
    for (int mt = 0; mt < 2; mt++) {
#pragma unroll
        for (int rr = 0; rr < 2; rr++) {
            const int row = wm * 32 + mt * 16 + (lane >> 2) + rr * 8;
            const int node = s_nid[row];
            const bool wr = (row < nrows) && (g_winner[node] == row0 + row);
#pragma unroll
            for (int nt = 0; nt < 8; nt++) {
                const int col = colbase + nt * 8;
                const int e = (mt * 8 + nt) * 4 + rr * 2;
                float z0 = fsigmoid(accA[e] + s_bsz[col]);
                float z1 = fsigmoid(accA[e + 1] + s_bsz[col + 1]);
                float2 h = *(const float2*)(hbase + sw512((uint32_t)row,
                                                          (uint32_t)(col * 4)));
                float o0 = (1.f - z0) * keep[e] + z0 * h.x;
                float o1 = (1.f - z1) * keep[e + 1] + z1 * h.y;
                if (wr) *(float2*)(out + (size_t)node * HDIM + col) = make_float2(o0, o1);
            }
        }
    }
}

// ---- launch ----
extern "C" void kernel_launch(void* const* d_in, const int* in_sizes, int n_in,
                              void* d_out, int out_size) {
    const int* ids = (const int*)d_in[0];
    const float* msgs = (const float*)d_in[1];
    const float* mem = (const float*)d_in[2];
    const float* Wih = (const float*)d_in[3];
    const float* Whh = (const float*)d_in[4];
    const float* bih = (const float*)d_in[5];
    const float* bhh = (const float*)d_in[6];
    float* out = (float*)d_out;

    const int batch = in_sizes[0];
    const int n_nodes = in_sizes[2] / HDIM;
    const int gcta = (batch + 127) / 128;
    const int periods = (gcta + 2) / 3;
    const int ccta = periods * 2;
    const int npc = (n_nodes + ccta - 1) / ccta;
    const int grid = periods * 5;

    cudaFuncSetAttribute(gru_kernel, cudaFuncAttributeMaxDynamicSharedMemorySize, SMEM_DYN);

    prep_kernel<<<256, 256>>>(Wih, Whh, n_nodes);
    winner_kernel<<<(batch + 255) / 256, 256>>>(ids, batch);
    gru_kernel<<<grid, 256, SMEM_DYN>>>(ids, msgs, mem, bih, bhh, out,
                                        batch, n_nodes, gcta, ccta, npc);
}

// round 7
// speedup vs baseline: 2.4253x; 1.0194x over previous
#include <cuda_runtime.h>
#include <cuda_bf16.h>
#include <cstdint>

#define HDIM 128
#define MAXNODES 1000000

// ---- scratch (no allocation allowed) ----
__device__ float g_Wihf[3 * HDIM * HDIM];   // tf32(RNA)-rounded weights
__device__ float g_Whhf[3 * HDIM * HDIM];
__device__ int g_winner[MAXNODES];

// ---- helpers ----
static __device__ __forceinline__ uint32_t smem_u32(const void* p) {
    uint32_t a;
    asm("{ .reg .u64 t; cvta.to.shared.u64 t, %1; cvt.u32.u64 %0, t; }" : "=r"(a) : "l"(p));
    return a;
}
static __device__ __forceinline__ uint32_t sw512(uint32_t r, uint32_t cb) {
    return (r << 9) + (cb ^ ((r & 7u) << 4));
}
static __device__ __forceinline__ uint32_t sw256(uint32_t r, uint32_t cb) {
    return (r << 8) + (cb ^ ((r & 7u) << 4));
}
static __device__ __forceinline__ uint32_t to_tf32(float x) {
    uint32_t u;
    asm("cvt.rna.tf32.f32 %0, %1;" : "=r"(u) : "f"(x));
    return u;
}
static __device__ __forceinline__ void ldm_x4(uint32_t* r, uint32_t addr) {
    asm volatile("ldmatrix.sync.aligned.m8n8.x4.shared.b16 {%0,%1,%2,%3}, [%4];"
                 : "=r"(r[0]), "=r"(r[1]), "=r"(r[2]), "=r"(r[3]) : "r"(addr));
}
static __device__ __forceinline__ void mma_tf32(float* d, const uint32_t* a,
                                                uint32_t b0, uint32_t b1) {
    asm volatile(
        "mma.sync.aligned.m16n8k8.row.col.f32.tf32.tf32.f32 "
        "{%0,%1,%2,%3}, {%4,%5,%6,%7}, {%8,%9}, {%0,%1,%2,%3};"
        : "+f"(d[0]), "+f"(d[1]), "+f"(d[2]), "+f"(d[3])
        : "r"(a[0]), "r"(a[1]), "r"(a[2]), "r"(a[3]), "r"(b0), "r"(b1));
}
static __device__ __forceinline__ void cp16(uint32_t saddr, const void* gptr) {
    asm volatile("cp.async.cg.shared.global [%0], [%1], 16;"
                 :: "r"(saddr), "l"(gptr) : "memory");
}
static __device__ __forceinline__ void cp16p(uint32_t saddr, const void* gptr, bool pred) {
    int sz = pred ? 16 : 0;
    asm volatile("cp.async.cg.shared.global [%0], [%1], 16, %2;"
                 :: "r"(saddr), "l"(gptr), "r"(sz) : "memory");
}
static __device__ __forceinline__ void cp_commit() {
    asm volatile("cp.async.commit_group;" ::: "memory");
}
template <int N> static __device__ __forceinline__ void cp_wait() {
    asm volatile("cp.async.wait_group %0;" :: "n"(N) : "memory");
}
static __device__ __forceinline__ float fsigmoid(float x) {
    float e = __expf(-x);
    float r;
    asm("rcp.approx.f32 %0, %1;" : "=f"(r) : "f"(1.0f + e));
    return r;
}
static __device__ __forceinline__ float ftanh(float x) {
    float y;
    asm("tanh.approx.f32 %0, %1;" : "=f"(y) : "f"(x));
    return y;
}

// ---- kernel 1: tf32-round weights (RNA) + winner reset ----
__global__ void prep_kernel(const float* __restrict__ Wih, const float* __restrict__ Whh,
                            int n_nodes) {
    int i = blockIdx.x * blockDim.x + threadIdx.x;
    int stride = gridDim.x * blockDim.x;
    for (int k = i; k < 3 * HDIM * HDIM; k += stride) {
        g_Wihf[k] = __uint_as_float(to_tf32(Wih[k]));
        g_Whhf[k] = __uint_as_float(to_tf32(Whh[k]));
    }
    for (int k = i; k < n_nodes; k += stride) g_winner[k] = -1;
}

// ---- kernel 2: last-writer-wins resolution ----
__global__ void winner_kernel(const int* __restrict__ ids, int batch) {
    int i = blockIdx.x * blockDim.x + threadIdx.x;
    if (i < batch) atomicMax(&g_winner[ids[i]], i);
}

// ---- one K=64 chunk of a 128x128 GEMM pass: acc += A[:,kc] @ Wchunk^T ----
static __device__ __forceinline__ void mma_chunk(uint32_t abase, uint32_t wbase,
                                                 float (&acc)[64], int lane, int wm, int wn,
                                                 int kc) {
    const uint32_t lr = (uint32_t)(lane & 7);
    const uint32_t lm = (uint32_t)(lane >> 3);
    const uint32_t a_row = (uint32_t)(wm * 32) + lr + ((lm & 1u) << 3);
    const uint32_t a_cb0 = (uint32_t)(kc * 256) + ((lm >> 1) << 4);
    const uint32_t b_row = (uint32_t)(wn * 64) + lr + ((lm >> 1) << 3);
    const uint32_t b_cb0 = (lm & 1u) << 4;
#pragma unroll
    for (int ks = 0; ks < 8; ks++) {
        uint32_t a[2][4];
        ldm_x4(a[0], abase + sw512(a_row, a_cb0 + (uint32_t)(ks * 32)));
        ldm_x4(a[1], abase + sw512(a_row + 16, a_cb0 + (uint32_t)(ks * 32)));
#pragma unroll
        for (int np = 0; np < 4; np++) {
            uint32_t b[4];
            ldm_x4(b, wbase + sw256(b_row + (uint32_t)(np * 16),
                                    b_cb0 + (uint32_t)(ks * 32)));
#pragma unroll
            for (int mt = 0; mt < 2; mt++) {
                mma_tf32(&acc[(mt * 8 + np * 2) * 4], a[mt], b[0], b[1]);
                mma_tf32(&acc[(mt * 8 + np * 2 + 1) * 4], a[mt], b[2], b[3]);
            }
        }
    }
}

// ---- fused kernel: role by blockIdx (2 copy : 3 GRU interleave) ----
// dyn smem (GRU role): X(64K) + H(64K) + 3 weight bufs (96K) = 224KB
#define SMEM_DYN (64 * 1024 + 64 * 1024 + 3 * 32 * 1024)

__global__ void __launch_bounds__(256, 1)
gru_kernel(const int* __restrict__ ids, const float* __restrict__ X,
           const float* __restrict__ Mem, const float* __restrict__ b_ih,
           const float* __restrict__ b_hh, float* __restrict__ out,
           int batch, int n_nodes, int gcta, int ccta, int npc) {
    const int p = blockIdx.x / 5;
    const int rrole = blockIdx.x % 5;

    const int tid = threadIdx.x;
    const int lane = tid & 31;
    const int wid = tid >> 5;

    if (rrole < 2) {
        // ================= COPY ROLE =================
        const int ci = p * 2 + rrole;
        if (ci >= ccta) return;
        const int node0 = ci * npc;
        int node1 = node0 + npc;
        if (node1 > n_nodes) node1 = n_nodes;
        // warp per 16 nodes; all loads unconditional & parallel, streaming hints
        for (int base = node0 + wid * 16; base < node1; base += 128) {
            const int lim = node1 - base;
            int w[16];
            float4 v[16];
#pragma unroll
            for (int j = 0; j < 16; j++)
                w[j] = (j < lim) ? __ldcs(g_winner + base + j) : 0;
#pragma unroll
            for (int j = 0; j < 16; j++)
                if (j < lim)
                    v[j] = __ldcs((const float4*)(Mem + (size_t)(base + j) * HDIM) + lane);
#pragma unroll
            for (int j = 0; j < 16; j++)
                if (j < lim && w[j] < 0)
                    __stcs((float4*)(out + (size_t)(base + j) * HDIM) + lane, v[j]);
        }
        return;
    }

    // ================= GRU ROLE =================
    const int g = p * 3 + (rrole - 2);
    if (g >= gcta) return;

    extern __shared__ char dsmem[];
    __shared__ int s_nid[128];
    __shared__ int s_win[128];
    __shared__ float s_bsr[128], s_bsz[128], s_bin[128], s_bhn[128];

    const int wm = wid & 3;
    const int wn = wid >> 2;

    const uint32_t sbase = smem_u32(dsmem);
    const uint32_t XS = sbase;
    const uint32_t HS = sbase + 64 * 1024;
    const uint32_t WB[3] = {sbase + 128 * 1024, sbase + 160 * 1024, sbase + 192 * 1024};

    const int row0 = g * 128;
    int nrows = batch - row0;
    if (nrows > 128) nrows = 128;

    // X tile: raw fp32 via cp.async (HW truncates to tf32 in MMA)
#pragma unroll
    for (int j = 0; j < 16; j++) {
        int idx = tid + j * 256;
        int r = idx >> 5, fq = idx & 31;
        cp16p(XS + sw512((uint32_t)r, (uint32_t)(fq << 4)),
              X + (size_t)(row0 + r) * HDIM + fq * 4, r < nrows);
    }
    // H tile: gathered rows, raw fp32 via cp.async (exact -> reused in epilogue)
    {
        int nidv[16];
#pragma unroll
        for (int j = 0; j < 16; j++) {
            int r = (tid + j * 256) >> 5;
            nidv[j] = (r < nrows) ? __ldg(ids + row0 + r) : 0;
        }
#pragma unroll
        for (int j = 0; j < 16; j++) {
            int idx = tid + j * 256;
            int r = idx >> 5, fq = idx & 31;
            cp16p(HS + sw512((uint32_t)r, (uint32_t)(fq << 4)),
                  Mem + (size_t)nidv[j] * HDIM + fq * 4, r < nrows);
        }
    }
    cp_commit();   // group: XH

    // per-row node id for epilogue (FIX: row == tid, own load)
    if (tid < 128) s_nid[tid] = (tid < nrows) ? __ldg(ids + row0 + tid) : 0;

    // weight chunk sources in pass order (float offsets):
    // P0: Wir, P1: Whr, P2: Whn, P3: Win, P4: Wiz, P5: Whz
    const float* wsrc[6];
    wsrc[0] = g_Wihf;          wsrc[1] = g_Whhf;
    wsrc[2] = g_Whhf + 32768;  wsrc[3] = g_Wihf + 32768;
    wsrc[4] = g_Wihf + 16384;  wsrc[5] = g_Whhf + 16384;

    // prefetch weight chunks 0 and 1 (chunk c: pass c>>1, kc = c&1, buffer c%3)
#pragma unroll
    for (int c = 0; c < 2; c++) {
        const float* src = wsrc[c >> 1] + (c & 1) * 64;
#pragma unroll
        for (int j = 0; j < 8; j++) {
            int ci = tid + j * 256;
            uint32_t n = (uint32_t)(ci >> 4), gi = (uint32_t)(ci & 15);
            cp16(WB[c] + sw256(n, gi << 4), src + (size_t)n * 128 + gi * 4);
        }
        cp_commit();
    }

    if (tid < 128) {
        s_win[tid] = (tid < nrows) ? __ldg(g_winner + s_nid[tid]) : -2;
        s_bsr[tid] = b_ih[tid] + b_hh[tid];
        s_bsz[tid] = b_ih[128 + tid] + b_hh[128 + tid];
        s_bin[tid] = b_ih[256 + tid];
        s_bhn[tid] = b_hh[256 + tid];
    }

    float accA[64], keep[64];
#pragma unroll
    for (int e = 0; e < 64; e++) accA[e] = 0.f;

    const int colbase = wn * 64 + 2 * (lane & 3);
    const uint32_t atile[6] = {XS, HS, HS, XS, XS, HS};

#pragma unroll
    for (int c = 0; c < 12; c++) {
        cp_wait<1>();          // chunk c (and XH on c==0) arrived
        __syncthreads();       // all warps done with chunk c-1's buffer
        if (c + 2 < 12) {      // prefetch chunk c+2 into ring buffer, overlaps MMA below
            const float* src = wsrc[(c + 2) >> 1] + ((c + 2) & 1) * 64;
            const uint32_t wb = WB[(c + 2) % 3];
#pragma unroll
            for (int j = 0; j < 8; j++) {
                int ci = tid + j * 256;
                uint32_t n = (uint32_t)(ci >> 4), gi = (uint32_t)(ci & 15);
                cp16(wb + sw256(n, gi << 4), src + (size_t)n * 128 + gi * 4);
            }
            cp_commit();
        }
        mma_chunk(atile[c >> 1], WB[c % 3], accA, lane, wm, wn, c & 1);
        if (c == 3) {           // r = sigmoid(X·Wir + H·Whr + b)
#pragma unroll
            for (int e = 0; e < 64; e++) {
                int col = colbase + (((e >> 2) & 7) << 3) + (e & 1);
                keep[e] = fsigmoid(accA[e] + s_bsr[col]);
                accA[e] = 0.f;
            }
        } else if (c == 5) {    // p = r * (H·Whn + bhn)
#pragma unroll
            for (int e = 0; e < 64; e++) {
                int col = colbase + (((e >> 2) & 7) << 3) + (e & 1);
                keep[e] = keep[e] * (accA[e] + s_bhn[col]);
                accA[e] = 0.f;
            }
        } else if (c == 7) {    // n = tanh(X·Win + bin + p)
#pragma unroll
            for (int e = 0; e < 64; e++) {
                int col = colbase + (((e >> 2) & 7) << 3) + (e & 1);
                keep[e] = ftanh(accA[e] + s_bin[col] + keep[e]);
                accA[e] = 0.f;
            }
        }
    }

    // epilogue: z = sigmoid(acc + bz); out = (1-z)*n + z*h  (h exact from SMEM H tile)
    const char* hbase = dsmem + 64 * 1024;
#pragma unroll
    for (int mt = 0; mt < 2; mt++) {
#pragma unroll
        for (int rr = 0; rr < 2; rr++) {
            const int row = wm * 32 + mt * 16 + (lane >> 2) + rr * 8;
            const int node = s_nid[row];
            const bool wr = (s_win[row] == row0 + row);
#pragma unroll
            for (int nt = 0; nt < 8; nt++) {
                const int col = colbase + nt * 8;
                const int e = (mt * 8 + nt) * 4 + rr * 2;
                float z0 = fsigmoid(accA[e] + s_bsz[col]);
                float z1 = fsigmoid(accA[e + 1] + s_bsz[col + 1]);
                float2 h = *(const float2*)(hbase + sw512((uint32_t)row,
                                                          (uint32_t)(col * 4)));
                float o0 = (1.f - z0) * keep[e] + z0 * h.x;
                float o1 = (1.f - z1) * keep[e + 1] + z1 * h.y;
                if (wr) *(float2*)(out + (size_t)node * HDIM + col) = make_float2(o0, o1);
            }
        }
    }
}

// ---- launch ----
extern "C" void kernel_launch(void* const* d_in, const int* in_sizes, int n_in,
                              void* d_out, int out_size) {
    const int* ids = (const int*)d_in[0];
    const float* msgs = (const float*)d_in[1];
    const float* mem = (const float*)d_in[2];
    const float* Wih = (const float*)d_in[3];
    const float* Whh = (const float*)d_in[4];
    const float* bih = (const float*)d_in[5];
    const float* bhh = (const float*)d_in[6];
    float* out = (float*)d_out;

    const int batch = in_sizes[0];
    const int n_nodes = in_sizes[2] / HDIM;
    const int gcta = (batch + 127) / 128;
    const int periods = (gcta + 2) / 3;
    const int ccta = periods * 2;
    const int npc = (n_nodes + ccta - 1) / ccta;
    const int grid = periods * 5;

    cudaFuncSetAttribute(gru_kernel, cudaFuncAttributeMaxDynamicSharedMemorySize, SMEM_DYN);

    prep_kernel<<<256, 256>>>(Wih, Whh, n_nodes);
    winner_kernel<<<(batch + 255) / 256, 256>>>(ids, batch);
    gru_kernel<<<grid, 256, SMEM_DYN>>>(ids, msgs, mem, bih, bhh, out,
                                        batch, n_nodes, gcta, ccta, npc);
}